// round 5
// baseline (speedup 1.0000x reference)
#include <cuda_runtime.h>

#define BB 8
#define NN 2048
#define CC 128
#define HH 4
#define DD 32
#define SS 3
#define KNB 16
#define KT 48
#define PP 16
#define MT 64          // GEMM m-tile

#define FULLMASK 0xffffffffu
typedef unsigned long long ull;

__device__ int   g_knn[BB * NN * KT];
__device__ float g_WkT[SS * CC * CC];
__device__ float g_Q[BB * NN * CC];
__device__ float g_V[BB * NN * CC];
__device__ float g_QK[SS * HH * BB * NN * CC];   // [i][h][b*n][c]  (96 MB)

// ---- f32x2 packed-FMA helpers (full fp32 precision, 2 FMA / instr) --------
__device__ __forceinline__ ull pk2(float lo, float hi) {
    ull r; asm("mov.b64 %0, {%1,%2};" : "=l"(r) : "f"(lo), "f"(hi)); return r;
}
__device__ __forceinline__ void fma2(ull& d, ull a, ull b) {
    asm("fma.rn.f32x2 %0, %1, %2, %0;" : "+l"(d) : "l"(a), "l"(b));
}
__device__ __forceinline__ float2 upk2(ull v) {
    float2 f; asm("mov.b64 {%0,%1}, %2;" : "=f"(f.x), "=f"(f.y) : "l"(v)); return f;
}

// ---------------------------------------------------------------------------
// Kernel 1: exact top-48 kNN per query + folded Wk transpose.
// ---------------------------------------------------------------------------
__global__ __launch_bounds__(256) void knn_kernel(const float* __restrict__ coord,
                                                  const float* __restrict__ Wk) {
    __shared__ float sx[NN], sy[NN], sz[NN], sq[NN];
    __shared__ ull s_buf[8][64];

    const int t = threadIdx.x;
    const int lane = t & 31, w = t >> 5;
    const int b = blockIdx.x / (NN / 8);
    const int n0 = (blockIdx.x % (NN / 8)) * 8;
    const float* cb = coord + (size_t)b * NN * 3;

    if (t < 24) {   // folded transpose: 2048 blocks x 24 = SS*CC*CC
        int id = blockIdx.x * 24 + t;
        int i = id >> 14, r = id & 16383;
        int c = r >> 7, j = r & 127;
        g_WkT[i * CC * CC + j * CC + c] = Wk[i * CC * CC + c * CC + j];
    }

    for (int j = t; j < NN; j += 256) {
        float x = cb[j * 3], y = cb[j * 3 + 1], z = cb[j * 3 + 2];
        sx[j] = x; sy[j] = y; sz[j] = z;
        sq[j] = fmaf(x, x, fmaf(y, y, z * z));
    }
    __syncthreads();

    const int n = n0 + w;
    const float ox = sx[n], oy = sy[n], oz = sz[n], osq = sq[n];

    unsigned kkey[64];
    unsigned m1 = 0xffffffffu, m2 = 0xffffffffu;
    #pragma unroll
    for (int s = 0; s < 64; s++) {
        int j = lane + (s << 5);
        float dot = fmaf(ox, sx[j], fmaf(oy, sy[j], oz * sz[j]));
        float d = fmaf(-2.0f, dot, osq + sq[j]);
        unsigned u = __float_as_uint(d);
        u = (u & 0x80000000u) ? ~u : (u | 0x80000000u);
        kkey[s] = u;
        if (u < m1) { m2 = m1; m1 = u; } else if (u < m2) { m2 = u; }
    }

    unsigned lo = __reduce_min_sync(FULLMASK, m1);
    unsigned hi = __reduce_max_sync(FULLMASK, m2);
    unsigned T;
    for (;;) {
        if (lo >= hi) { T = lo; break; }
        unsigned mid = lo + ((hi - lo) >> 1);
        unsigned c = 0;
        #pragma unroll
        for (int s = 0; s < 64; s++) c += (kkey[s] <= mid) ? 1u : 0u;
        c = __reduce_add_sync(FULLMASK, c);
        if (c == KT) { T = mid; break; }
        if (c > KT) hi = mid; else lo = mid + 1;
    }

    s_buf[w][lane] = ~0ull;
    s_buf[w][lane + 32] = ~0ull;
    __syncwarp();
    int base = 0;
    #pragma unroll
    for (int s = 0; s < 64; s++) {
        bool q = (kkey[s] <= T);
        unsigned m = __ballot_sync(FULLMASK, q);
        if (q) {
            int pos = base + __popc(m & ((1u << lane) - 1u));
            if (pos < 64)
                s_buf[w][pos] = ((ull)kkey[s] << 32) | (unsigned)(lane + (s << 5));
        }
        base += __popc(m);
    }
    __syncwarp();

    ull v0 = s_buf[w][lane];
    ull v1 = s_buf[w][lane + 32];
    #pragma unroll
    for (int k2 = 2; k2 <= 64; k2 <<= 1) {
        #pragma unroll
        for (int j2 = k2 >> 1; j2 > 0; j2 >>= 1) {
            if (j2 == 32) {
                ull a = v0 < v1 ? v0 : v1;
                ull bm = v0 < v1 ? v1 : v0;
                v0 = a; v1 = bm;
            } else {
                bool low = ((lane & j2) == 0);
                bool up0 = ((lane & k2) == 0);
                bool up1 = (((lane + 32) & k2) == 0);
                ull o0 = __shfl_xor_sync(FULLMASK, v0, j2);
                ull o1 = __shfl_xor_sync(FULLMASK, v1, j2);
                bool t0 = (low == up0);
                bool t1 = (low == up1);
                v0 = t0 ? (v0 < o0 ? v0 : o0) : (v0 > o0 ? v0 : o0);
                v1 = t1 ? (v1 < o1 ? v1 : o1) : (v1 > o1 ? v1 : o1);
            }
        }
    }

    int* outp = g_knn + ((size_t)b * NN + n) * KT;
    outp[lane] = (int)(v0 & 0xffffffffu);
    if (lane < KT - 32) outp[32 + lane] = (int)(v1 & 0xffffffffu);
}

// ---------------------------------------------------------------------------
// Register-tiled GEMM body: O[m0..m0+64][0..128) = A[m][0..KD) @ W[KD][128]
// 256 threads, 32 outputs/thread (8 m x 4 n), f32x2 accumulators.
// ---------------------------------------------------------------------------
template<int KD, bool HASBIAS>
__device__ __forceinline__ void gemm_body(const float* __restrict__ A,
                                          const float* __restrict__ W,
                                          const float* __restrict__ bias,
                                          float* __restrict__ O) {
    __shared__ float XsT[KD][72];
    const int t = threadIdx.x;
    const int tx = t & 31, ty = t >> 5;
    const int m0 = blockIdx.x * MT;

    constexpr int NS = MT * KD / 4;
    #pragma unroll
    for (int s = t; s < NS; s += 256) {
        int m = s / (KD / 4), k4 = s % (KD / 4);
        float4 v = *(const float4*)&A[(size_t)(m0 + m) * CC + 4 * k4];
        XsT[4 * k4 + 0][m] = v.x;
        XsT[4 * k4 + 1][m] = v.y;
        XsT[4 * k4 + 2][m] = v.z;
        XsT[4 * k4 + 3][m] = v.w;
    }
    __syncthreads();

    ull acc[4][4];
    #pragma unroll
    for (int mp = 0; mp < 4; mp++)
        #pragma unroll
        for (int c = 0; c < 4; c++) acc[mp][c] = 0;

    #pragma unroll 8
    for (int k = 0; k < KD; k++) {
        float4 wv = __ldg(&((const float4*)W)[k * 32 + tx]);
        ull w0 = pk2(wv.x, wv.x), w1 = pk2(wv.y, wv.y);
        ull w2 = pk2(wv.z, wv.z), w3 = pk2(wv.w, wv.w);
        ulonglong2 xa = *(const ulonglong2*)&XsT[k][ty * 8];
        ulonglong2 xb = *(const ulonglong2*)&XsT[k][ty * 8 + 4];
        fma2(acc[0][0], xa.x, w0); fma2(acc[0][1], xa.x, w1);
        fma2(acc[0][2], xa.x, w2); fma2(acc[0][3], xa.x, w3);
        fma2(acc[1][0], xa.y, w0); fma2(acc[1][1], xa.y, w1);
        fma2(acc[1][2], xa.y, w2); fma2(acc[1][3], xa.y, w3);
        fma2(acc[2][0], xb.x, w0); fma2(acc[2][1], xb.x, w1);
        fma2(acc[2][2], xb.x, w2); fma2(acc[2][3], xb.x, w3);
        fma2(acc[3][0], xb.y, w0); fma2(acc[3][1], xb.y, w1);
        fma2(acc[3][2], xb.y, w2); fma2(acc[3][3], xb.y, w3);
    }

    float4 bb = make_float4(0.f, 0.f, 0.f, 0.f);
    if (HASBIAS) bb = *(const float4*)&bias[tx * 4];
    #pragma unroll
    for (int mp = 0; mp < 4; mp++) {
        float2 f0 = upk2(acc[mp][0]), f1 = upk2(acc[mp][1]);
        float2 f2 = upk2(acc[mp][2]), f3 = upk2(acc[mp][3]);
        int m = m0 + ty * 8 + 2 * mp;
        float4 r0 = make_float4(f0.x + bb.x, f1.x + bb.y, f2.x + bb.z, f3.x + bb.w);
        float4 r1 = make_float4(f0.y + bb.x, f1.y + bb.y, f2.y + bb.z, f3.y + bb.w);
        *(float4*)&O[(size_t)m * CC + tx * 4] = r0;
        *(float4*)&O[(size_t)(m + 1) * CC + tx * 4] = r1;
    }
}

__global__ __launch_bounds__(256, 4) void gemm_qv_kernel(
    const float* __restrict__ pcd,
    const float* __restrict__ Wq, const float* __restrict__ bq,
    const float* __restrict__ Wv, const float* __restrict__ bv) {
    if (blockIdx.y == 0) gemm_body<CC, true>(pcd, Wq, bq, g_Q);
    else                 gemm_body<CC, true>(pcd, Wv, bv, g_V);
}

__global__ __launch_bounds__(256, 4) void gemm_qk_kernel() {
    const int y = blockIdx.y;            // i*4 + h
    const int i = y >> 2, h = y & 3;
    gemm_body<DD, false>(g_Q + DD * h,
                         g_WkT + i * CC * CC + DD * h * CC,
                         nullptr,
                         g_QK + (size_t)y * (BB * NN) * CC);
}

// ---------------------------------------------------------------------------
// Kernel 3: slim attention (16 points / 256-thread block).
// qk register-cached from g_QK; own-dot folded in as chunk 4.
// ---------------------------------------------------------------------------
__global__ __launch_bounds__(256, 3) void attn_kernel(
    const float* __restrict__ pcd,
    const float* __restrict__ bk,
    float* __restrict__ out)
{
    __shared__ float s_logit[PP][HH][KT];
    __shared__ float s_own[PP][HH][SS];
    __shared__ float s_qb[PP][HH][SS];
    __shared__ float s_attn[PP][HH];

    const int t = threadIdx.x;
    const int lane = t & 31, w = t >> 5;
    const int b = blockIdx.x / (NN / PP);
    const int n0 = (blockIdx.x % (NN / PP)) * PP;
    const size_t gbase = (size_t)b * NN;
    const float* pb = pcd + gbase * CC;

    // --- qb = q . bk[i] (head slice), t < 192 ---
    if (t < PP * HH * SS) {
        int p = t / 12, r = t % 12, i = r >> 2, h = r & 3;
        const float* qr = g_Q + (gbase + n0 + p) * CC + DD * h;
        const float* bkr = bk + i * CC + DD * h;
        float s = 0.0f;
        #pragma unroll
        for (int d = 0; d < DD; d++) s = fmaf(qr[d], bkr[d], s);
        s_qb[p][h][i] = s;
    }

    // --- logits: warp w owns points 2w, 2w+1 ---
    const int g = lane & 7, kq = lane >> 3;
    #pragma unroll 1
    for (int i = 0; i < SS; i++) {
        #pragma unroll
        for (int pp = 0; pp < 2; pp++) {
            const int p = 2 * w + pp;
            const int nloc = n0 + p;
            const int* kn = g_knn + (gbase + nloc) * KT + i * KNB;
            int idxreg = (lane < KNB) ? kn[lane] : 0;
            #pragma unroll
            for (int ph = 0; ph < 2; ph++) {
                const float* qk0 = g_QK +
                    ((size_t)(i * 4 + 2 * ph) * (BB * NN) + gbase + nloc) * CC;
                const float* qk1 = qk0 + (size_t)(BB * NN) * CC;
                ulonglong2 q0[4], q1[4];
                #pragma unroll
                for (int m = 0; m < 4; m++) {
                    q0[m] = *(const ulonglong2*)&qk0[4 * g + 32 * m];
                    q1[m] = *(const ulonglong2*)&qk1[4 * g + 32 * m];
                }
                #pragma unroll
                for (int ch = 0; ch < 5; ch++) {
                    int j = (ch < 4) ? __shfl_sync(FULLMASK, idxreg, 4 * ch + kq)
                                     : nloc;
                    const float* rowj = pb + (size_t)j * CC;
                    ull a0 = 0, a1 = 0;
                    #pragma unroll
                    for (int m = 0; m < 4; m++) {
                        ulonglong2 nb = *(const ulonglong2*)&rowj[4 * g + 32 * m];
                        fma2(a0, nb.x, q0[m].x); fma2(a0, nb.y, q0[m].y);
                        fma2(a1, nb.x, q1[m].x); fma2(a1, nb.y, q1[m].y);
                    }
                    float2 f0 = upk2(a0), f1 = upk2(a1);
                    float s0 = f0.x + f0.y, s1 = f1.x + f1.y;
                    #pragma unroll
                    for (int off = 1; off <= 4; off <<= 1) {
                        s0 += __shfl_xor_sync(FULLMASK, s0, off);
                        s1 += __shfl_xor_sync(FULLMASK, s1, off);
                    }
                    if (ch < 4) {
                        if (g == 0) s_logit[p][2 * ph][i * KNB + 4 * ch + kq] = s0;
                        if (g == 1) s_logit[p][2 * ph + 1][i * KNB + 4 * ch + kq] = s1;
                    } else if (kq == 0) {
                        if (g == 0) s_own[p][2 * ph][i] = s0;
                        if (g == 1) s_own[p][2 * ph + 1][i] = s1;
                    }
                }
            }
        }
    }
    __syncthreads();

    // --- softmax + attn accumulate: t < 64 owns (p, h) ---
    if (t < PP * HH) {
        const int p = t >> 2, h = t & 3;
        const float inv = 0.17677669529663687f;   // 1/sqrt(32)
        float accA = 0.0f;
        #pragma unroll
        for (int i = 0; i < SS; i++) {
            float corr = s_qb[p][h][i] - s_own[p][h][i];
            float l[KNB];
            float mx = -1e30f;
            #pragma unroll
            for (int k = 0; k < KNB; k++) {
                l[k] = inv * (s_logit[p][h][i * KNB + k] + corr);
                mx = fmaxf(mx, l[k]);
            }
            float se = 0.0f, sl = 0.0f;
            #pragma unroll
            for (int k = 0; k < KNB; k++) {
                float e = __expf(l[k] - mx);
                se += e;
                sl = fmaf(e, l[k], sl);
            }
            accA += sl / se;
        }
        s_attn[p][h] = accA;
    }
    __syncthreads();

    // --- out = attn * V ---
    #pragma unroll
    for (int s = t; s < PP * 32; s += 256) {
        int p = s >> 5, c4 = s & 31;
        size_t n = gbase + n0 + p;
        float4 vv = *(const float4*)&g_V[n * CC + 4 * c4];
        float a = s_attn[p][c4 >> 3];
        float4 r = make_float4(a * vv.x, a * vv.y, a * vv.z, a * vv.w);
        *(float4*)&out[n * CC + 4 * c4] = r;
    }
}

// ---------------------------------------------------------------------------
extern "C" void kernel_launch(void* const* d_in, const int* in_sizes, int n_in,
                              void* d_out, int out_size) {
    (void)in_sizes; (void)n_in; (void)out_size;
    const float* pcd   = (const float*)d_in[0];
    const float* coord = (const float*)d_in[1];
    const float* Wq    = (const float*)d_in[3];
    const float* bq    = (const float*)d_in[4];
    const float* Wk    = (const float*)d_in[5];
    const float* bk    = (const float*)d_in[6];
    const float* Wv    = (const float*)d_in[7];
    const float* bv    = (const float*)d_in[8];
    float* out = (float*)d_out;

    knn_kernel<<<BB * NN / 8, 256>>>(coord, Wk);
    gemm_qv_kernel<<<dim3(BB * NN / MT, 2), 256>>>(pcd, Wq, bq, Wv, bv);
    gemm_qk_kernel<<<dim3(BB * NN / MT, SS * HH), 256>>>();
    attn_kernel<<<BB * NN / PP, 256>>>(pcd, bk, out);
}

// round 6
// speedup vs baseline: 1.3184x; 1.3184x over previous
#include <cuda_runtime.h>

#define BB 8
#define NN 2048
#define BN (BB * NN)
#define CC 128
#define HH 4
#define DD 32
#define SS 3
#define KNB 16
#define KT 48
#define MT 64          // GEMM m-tile
#define APP 8          // points per attn block (1 warp each)
#define NJOB 54        // 48 nbr + 3 own + 3 bk

#define FULLMASK 0xffffffffu
typedef unsigned long long ull;

__device__ int   g_knn[BN * KT];
__device__ float g_Q[BN * CC];
__device__ float g_V[BN * CC];
__device__ float g_KF[(SS * BN + SS) * CC];   // + SS rows of bk at the tail

// ---- f32x2 packed-FMA helpers (full fp32 precision, 2 FMA / instr) --------
__device__ __forceinline__ ull pk2(float lo, float hi) {
    ull r; asm("mov.b64 %0, {%1,%2};" : "=l"(r) : "f"(lo), "f"(hi)); return r;
}
__device__ __forceinline__ void fma2(ull& d, ull a, ull b) {
    asm("fma.rn.f32x2 %0, %1, %2, %0;" : "+l"(d) : "l"(a), "l"(b));
}
__device__ __forceinline__ float2 upk2(ull v) {
    float2 f; asm("mov.b64 {%0,%1}, %2;" : "=f"(f.x), "=f"(f.y) : "l"(v)); return f;
}

// ---------------------------------------------------------------------------
// Kernel 1: exact top-48 kNN per query.
// ---------------------------------------------------------------------------
__global__ __launch_bounds__(256) void knn_kernel(const float* __restrict__ coord) {
    __shared__ float sx[NN], sy[NN], sz[NN], sq[NN];
    __shared__ ull s_buf[8][64];

    const int t = threadIdx.x;
    const int lane = t & 31, w = t >> 5;
    const int b = blockIdx.x / (NN / 8);
    const int n0 = (blockIdx.x % (NN / 8)) * 8;
    const float* cb = coord + (size_t)b * NN * 3;

    for (int j = t; j < NN; j += 256) {
        float x = cb[j * 3], y = cb[j * 3 + 1], z = cb[j * 3 + 2];
        sx[j] = x; sy[j] = y; sz[j] = z;
        sq[j] = fmaf(x, x, fmaf(y, y, z * z));
    }
    __syncthreads();

    const int n = n0 + w;
    const float ox = sx[n], oy = sy[n], oz = sz[n], osq = sq[n];

    unsigned kkey[64];
    unsigned m1 = 0xffffffffu, m2 = 0xffffffffu;
    #pragma unroll
    for (int s = 0; s < 64; s++) {
        int j = lane + (s << 5);
        float dot = fmaf(ox, sx[j], fmaf(oy, sy[j], oz * sz[j]));
        float d = fmaf(-2.0f, dot, osq + sq[j]);
        unsigned u = __float_as_uint(d);
        u = (u & 0x80000000u) ? ~u : (u | 0x80000000u);
        kkey[s] = u;
        if (u < m1) { m2 = m1; m1 = u; } else if (u < m2) { m2 = u; }
    }

    unsigned lo = __reduce_min_sync(FULLMASK, m1);
    unsigned hi = __reduce_max_sync(FULLMASK, m2);
    unsigned T;
    for (;;) {
        if (lo >= hi) { T = lo; break; }
        unsigned mid = lo + ((hi - lo) >> 1);
        unsigned c = 0;
        #pragma unroll
        for (int s = 0; s < 64; s++) c += (kkey[s] <= mid) ? 1u : 0u;
        c = __reduce_add_sync(FULLMASK, c);
        if (c == KT) { T = mid; break; }
        if (c > KT) hi = mid; else lo = mid + 1;
    }

    s_buf[w][lane] = ~0ull;
    s_buf[w][lane + 32] = ~0ull;
    __syncwarp();
    int base = 0;
    #pragma unroll
    for (int s = 0; s < 64; s++) {
        bool q = (kkey[s] <= T);
        unsigned m = __ballot_sync(FULLMASK, q);
        if (q) {
            int pos = base + __popc(m & ((1u << lane) - 1u));
            if (pos < 64)
                s_buf[w][pos] = ((ull)kkey[s] << 32) | (unsigned)(lane + (s << 5));
        }
        base += __popc(m);
    }
    __syncwarp();

    ull v0 = s_buf[w][lane];
    ull v1 = s_buf[w][lane + 32];
    #pragma unroll
    for (int k2 = 2; k2 <= 64; k2 <<= 1) {
        #pragma unroll
        for (int j2 = k2 >> 1; j2 > 0; j2 >>= 1) {
            if (j2 == 32) {
                ull a = v0 < v1 ? v0 : v1;
                ull bm = v0 < v1 ? v1 : v0;
                v0 = a; v1 = bm;
            } else {
                bool low = ((lane & j2) == 0);
                bool up0 = ((lane & k2) == 0);
                bool up1 = (((lane + 32) & k2) == 0);
                ull o0 = __shfl_xor_sync(FULLMASK, v0, j2);
                ull o1 = __shfl_xor_sync(FULLMASK, v1, j2);
                bool t0 = (low == up0);
                bool t1 = (low == up1);
                v0 = t0 ? (v0 < o0 ? v0 : o0) : (v0 > o0 ? v0 : o0);
                v1 = t1 ? (v1 < o1 ? v1 : o1) : (v1 > o1 ? v1 : o1);
            }
        }
    }

    int* outp = g_knn + ((size_t)b * NN + n) * KT;
    outp[lane] = (int)(v0 & 0xffffffffu);
    if (lane < KT - 32) outp[32 + lane] = (int)(v1 & 0xffffffffu);
}

// ---------------------------------------------------------------------------
// Register-tiled GEMM body: O[m0..m0+64][0..128) = A @ W (+bias)
// ---------------------------------------------------------------------------
__device__ __forceinline__ void gemm_body(const float* __restrict__ A,
                                          const float* __restrict__ W,
                                          const float* __restrict__ bias,
                                          float* __restrict__ O) {
    __shared__ float XsT[CC][72];
    const int t = threadIdx.x;
    const int tx = t & 31, ty = t >> 5;
    const int m0 = blockIdx.x * MT;

    #pragma unroll
    for (int s = t; s < MT * CC / 4; s += 256) {
        int m = s >> 5, k4 = s & 31;
        float4 v = *(const float4*)&A[(size_t)(m0 + m) * CC + 4 * k4];
        XsT[4 * k4 + 0][m] = v.x;
        XsT[4 * k4 + 1][m] = v.y;
        XsT[4 * k4 + 2][m] = v.z;
        XsT[4 * k4 + 3][m] = v.w;
    }
    __syncthreads();

    ull acc[4][4];
    #pragma unroll
    for (int mp = 0; mp < 4; mp++)
        #pragma unroll
        for (int c = 0; c < 4; c++) acc[mp][c] = 0;

    #pragma unroll 8
    for (int k = 0; k < CC; k++) {
        float4 wv = __ldg(&((const float4*)W)[k * 32 + tx]);
        ull w0 = pk2(wv.x, wv.x), w1 = pk2(wv.y, wv.y);
        ull w2 = pk2(wv.z, wv.z), w3 = pk2(wv.w, wv.w);
        ulonglong2 xa = *(const ulonglong2*)&XsT[k][ty * 8];
        ulonglong2 xb = *(const ulonglong2*)&XsT[k][ty * 8 + 4];
        fma2(acc[0][0], xa.x, w0); fma2(acc[0][1], xa.x, w1);
        fma2(acc[0][2], xa.x, w2); fma2(acc[0][3], xa.x, w3);
        fma2(acc[1][0], xa.y, w0); fma2(acc[1][1], xa.y, w1);
        fma2(acc[1][2], xa.y, w2); fma2(acc[1][3], xa.y, w3);
        fma2(acc[2][0], xb.x, w0); fma2(acc[2][1], xb.x, w1);
        fma2(acc[2][2], xb.x, w2); fma2(acc[2][3], xb.x, w3);
        fma2(acc[3][0], xb.y, w0); fma2(acc[3][1], xb.y, w1);
        fma2(acc[3][2], xb.y, w2); fma2(acc[3][3], xb.y, w3);
    }

    float4 bb = *(const float4*)&bias[tx * 4];
    #pragma unroll
    for (int mp = 0; mp < 4; mp++) {
        float2 f0 = upk2(acc[mp][0]), f1 = upk2(acc[mp][1]);
        float2 f2 = upk2(acc[mp][2]), f3 = upk2(acc[mp][3]);
        int m = m0 + ty * 8 + 2 * mp;
        float4 r0 = make_float4(f0.x + bb.x, f1.x + bb.y, f2.x + bb.z, f3.x + bb.w);
        float4 r1 = make_float4(f0.y + bb.x, f1.y + bb.y, f2.y + bb.z, f3.y + bb.w);
        *(float4*)&O[(size_t)m * CC + tx * 4] = r0;
        *(float4*)&O[(size_t)(m + 1) * CC + tx * 4] = r1;
    }
}

// y=0: Q   y=1: V   y=2..4: Kf[i] = pcd@Wk[i] + bk[i]
__global__ __launch_bounds__(256, 4) void gemm_all_kernel(
    const float* __restrict__ pcd,
    const float* __restrict__ Wq, const float* __restrict__ bq,
    const float* __restrict__ Wk, const float* __restrict__ bk,
    const float* __restrict__ Wv, const float* __restrict__ bv) {
    const int y = blockIdx.y;
    if (y == 0)      gemm_body(pcd, Wq, bq, g_Q);
    else if (y == 1) gemm_body(pcd, Wv, bv, g_V);
    else {
        const int i = y - 2;
        if (blockIdx.x == 0 && threadIdx.x < CC)   // bk rows at g_KF tail
            g_KF[(size_t)(SS * BN + i) * CC + threadIdx.x] = bk[i * CC + threadIdx.x];
        gemm_body(pcd, Wk + i * CC * CC, bk + i * CC, g_KF + (size_t)i * BN * CC);
    }
}

// ---------------------------------------------------------------------------
// Kernel 3: attention via Kf gathers. One warp per point, 8 points/block.
// 54 jobs/point (48 nbr + 3 own + 3 bk), chunks of 4 jobs, 8 lanes/job.
// ---------------------------------------------------------------------------
__global__ __launch_bounds__(256, 6) void attn_kernel(
    float* __restrict__ out)
{
    __shared__ int   s_kn[APP][KT];
    __shared__ float s_raw[APP][HH][56];
    __shared__ float s_attn[APP][HH];

    const int t = threadIdx.x;
    const int lane = t & 31, w = t >> 5;
    const int g = lane & 7, kq = lane >> 3;
    const int b = blockIdx.x / (NN / APP);
    const int n0 = (blockIdx.x % (NN / APP)) * APP;
    const int gbase = b * NN;

    for (int idx = t; idx < APP * KT; idx += 256) {
        int p = idx / KT, j = idx % KT;
        s_kn[p][j] = g_knn[(size_t)(gbase + n0 + p) * KT + j];
    }
    __syncthreads();

    const int n = n0 + w;

    // q registers: lane g covers cols 4g+32m, m=0..3
    ulonglong2 qm[4];
    {
        const float* qrow = g_Q + (size_t)(gbase + n) * CC;
        #pragma unroll
        for (int m = 0; m < 4; m++)
            qm[m] = *(const ulonglong2*)&qrow[4 * g + 32 * m];
    }

    // job index -> extended row in g_KF
    auto job_ext = [&](int jid) -> int {
        int i = (jid >= 36) ? 2 : (jid >= 18 ? 1 : 0);
        int r = jid - 18 * i;
        if (r < 16)  return i * BN + gbase + s_kn[w][i * KNB + r];
        if (r == 16) return i * BN + gbase + n;
        return SS * BN + i;
    };
    int je0 = job_ext(lane);
    int je1 = (lane < NJOB - 32) ? job_ext(32 + lane) : je0;

    #pragma unroll
    for (int ch = 0; ch < 14; ch++) {
        int jid = (ch < 8) ? (4 * ch + kq) : (32 + 4 * (ch - 8) + kq);
        int src = (ch < 8) ? (4 * ch + kq) : (4 * (ch - 8) + kq);
        int jext = __shfl_sync(FULLMASK, (ch < 8) ? je0 : je1, src);
        const float* kf = g_KF + (size_t)jext * CC;

        ull a0 = 0, a1 = 0, a2 = 0, a3 = 0;
        {
            ulonglong2 nb0 = *(const ulonglong2*)&kf[4 * g];
            ulonglong2 nb1 = *(const ulonglong2*)&kf[4 * g + 32];
            ulonglong2 nb2 = *(const ulonglong2*)&kf[4 * g + 64];
            ulonglong2 nb3 = *(const ulonglong2*)&kf[4 * g + 96];
            fma2(a0, nb0.x, qm[0].x); fma2(a0, nb0.y, qm[0].y);
            fma2(a1, nb1.x, qm[1].x); fma2(a1, nb1.y, qm[1].y);
            fma2(a2, nb2.x, qm[2].x); fma2(a2, nb2.y, qm[2].y);
            fma2(a3, nb3.x, qm[3].x); fma2(a3, nb3.y, qm[3].y);
        }
        float2 f0 = upk2(a0), f1 = upk2(a1), f2 = upk2(a2), f3 = upk2(a3);
        float s0 = f0.x + f0.y, s1 = f1.x + f1.y;
        float s2 = f2.x + f2.y, s3 = f3.x + f3.y;
        #pragma unroll
        for (int off = 1; off <= 4; off <<= 1) {
            s0 += __shfl_xor_sync(FULLMASK, s0, off);
            s1 += __shfl_xor_sync(FULLMASK, s1, off);
            s2 += __shfl_xor_sync(FULLMASK, s2, off);
            s3 += __shfl_xor_sync(FULLMASK, s3, off);
        }
        float val = (g == 0) ? s0 : (g == 1) ? s1 : (g == 2) ? s2 : s3;
        if (g < 4 && jid < NJOB) s_raw[w][g][jid] = val;
    }
    __syncthreads();

    // --- softmax + attn accumulate: t < 32 owns (p = t>>2, h = t&3) ---
    if (t < APP * HH) {
        const int p = t >> 2, h = t & 3;
        const float inv = 0.17677669529663687f;   // 1/sqrt(32)
        float accA = 0.0f;
        #pragma unroll
        for (int i = 0; i < SS; i++) {
            const float* raw = &s_raw[p][h][i * 18];
            float corr = raw[17] - raw[16];       // q.bk - q.Kf'[n]
            float l[KNB];
            float mx = -1e30f;
            #pragma unroll
            for (int k = 0; k < KNB; k++) {
                l[k] = inv * (raw[k] + corr);
                mx = fmaxf(mx, l[k]);
            }
            float se = 0.0f, sl = 0.0f;
            #pragma unroll
            for (int k = 0; k < KNB; k++) {
                float e = __expf(l[k] - mx);
                se += e;
                sl = fmaf(e, l[k], sl);
            }
            accA += sl / se;
        }
        s_attn[p][h] = accA;
    }
    __syncthreads();

    // --- out = attn * V : 256 threads = 8 points x 32 float4 ---
    {
        int p = t >> 5, c4 = t & 31;
        size_t nn = (size_t)gbase + n0 + p;
        float4 vv = *(const float4*)&g_V[nn * CC + 4 * c4];
        float a = s_attn[p][c4 >> 3];
        float4 r = make_float4(a * vv.x, a * vv.y, a * vv.z, a * vv.w);
        *(float4*)&out[nn * CC + 4 * c4] = r;
    }
}

// ---------------------------------------------------------------------------
extern "C" void kernel_launch(void* const* d_in, const int* in_sizes, int n_in,
                              void* d_out, int out_size) {
    (void)in_sizes; (void)n_in; (void)out_size;
    const float* pcd   = (const float*)d_in[0];
    const float* coord = (const float*)d_in[1];
    const float* Wq    = (const float*)d_in[3];
    const float* bq    = (const float*)d_in[4];
    const float* Wk    = (const float*)d_in[5];
    const float* bk    = (const float*)d_in[6];
    const float* Wv    = (const float*)d_in[7];
    const float* bv    = (const float*)d_in[8];
    float* out = (float*)d_out;

    knn_kernel<<<BN / 8, 256>>>(coord);
    gemm_all_kernel<<<dim3(BN / MT, 2 + SS), 256>>>(pcd, Wq, bq, Wk, bk, Wv, bv);
    attn_kernel<<<BN / APP, 256>>>(out);
}

// round 7
// speedup vs baseline: 1.4507x; 1.1003x over previous
#include <cuda_runtime.h>

#define BB 8
#define NN 2048
#define BN (BB * NN)
#define CC 128
#define HH 4
#define DD 32
#define SS 3
#define KNB 16
#define KT 48
#define MT 64          // GEMM m-tile
#define APP 8          // points per attn block (1 warp each)
#define NJOB 54        // 48 nbr + 3 own + 3 bk
#define CAP 256        // knn candidate capacity per warp

#define FULLMASK 0xffffffffu
typedef unsigned long long ull;

__device__ int   g_knn[BN * KT];
__device__ float g_Q[BN * CC];
__device__ float g_V[BN * CC];
__device__ float g_KF[(SS * BN + SS) * CC];   // + SS rows of bk at the tail

// ---- f32x2 packed-FMA helpers (full fp32 precision, 2 FMA / instr) --------
__device__ __forceinline__ ull pk2(float lo, float hi) {
    ull r; asm("mov.b64 %0, {%1,%2};" : "=l"(r) : "f"(lo), "f"(hi)); return r;
}
__device__ __forceinline__ void fma2(ull& d, ull a, ull b) {
    asm("fma.rn.f32x2 %0, %1, %2, %0;" : "+l"(d) : "l"(a), "l"(b));
}
__device__ __forceinline__ float2 upk2(ull v) {
    float2 f; asm("mov.b64 {%0,%1}, %2;" : "=f"(f.x), "=f"(f.y) : "l"(v)); return f;
}

// ---------------------------------------------------------------------------
// Shared-memory layouts for the fused kernel (union via dynamic smem)
// ---------------------------------------------------------------------------
struct KnnS {
    float4 c4[NN];          // (x, y, z, |p|^2)       32 KB
    ull    cand[8][CAP];    // compacted candidates   16 KB
    ull    buf[8][64];      // sort buffer             4 KB
};
struct GemmS { float XsT[CC][72]; };                // 36.9 KB

// ---------------------------------------------------------------------------
// kNN body: exact top-48 per query (one warp per query, 8 queries/block).
// ---------------------------------------------------------------------------
__device__ __forceinline__ void knn_body(char* smraw, const float* __restrict__ coord,
                                         int bx) {
    KnnS* K = (KnnS*)smraw;
    const int t = threadIdx.x;
    const int lane = t & 31, w = t >> 5;
    const int b = bx >> 8;                 // 256 blocks per batch
    const int n0 = (bx & 255) * 8;
    const float* cb = coord + (size_t)b * NN * 3;

    for (int j = t; j < NN; j += 256) {
        float x = cb[3 * j], y = cb[3 * j + 1], z = cb[3 * j + 2];
        K->c4[j] = make_float4(x, y, z, fmaf(x, x, fmaf(y, y, z * z)));
    }
    __syncthreads();

    const int n = n0 + w;
    const float4 o = K->c4[n];

    unsigned kkey[64];
    unsigned m1 = 0xffffffffu, m2 = 0xffffffffu;
    #pragma unroll
    for (int s = 0; s < 64; s++) {
        int j = lane + (s << 5);
        float4 c = K->c4[j];
        float dot = fmaf(o.x, c.x, fmaf(o.y, c.y, o.z * c.z));
        float d = fmaf(-2.0f, dot, o.w + c.w);         // matches reference formula
        unsigned u = __float_as_uint(d);
        u = (u & 0x80000000u) ? ~u : (u | 0x80000000u);
        kkey[s] = u;
        if (u < m1) { m2 = m1; m1 = u; } else if (u < m2) { m2 = u; }
    }

    unsigned lo = __reduce_min_sync(FULLMASK, m1);
    unsigned hi = __reduce_max_sync(FULLMASK, m2);    // >= 64 keys <= hi

    // ---- compact all keys <= hi into smem (count in base) ----
    int base = 0;
    #pragma unroll
    for (int s = 0; s < 64; s++) {
        bool q = (kkey[s] <= hi);
        unsigned mm = __ballot_sync(FULLMASK, q);
        if (q) {
            int pos = base + __popc(mm & ((1u << lane) - 1u));
            if (pos < CAP)
                K->cand[w][pos] = ((ull)kkey[s] << 32) | (unsigned)(lane + (s << 5));
        }
        base += __popc(mm);
    }
    __syncwarp();

    unsigned T;
    if (base <= CAP) {
        // ---- search over <= 8 candidates per lane ----
        unsigned ck[8];
        #pragma unroll
        for (int sl = 0; sl < 8; sl++) {
            int p = lane + (sl << 5);
            ck[sl] = (p < base) ? (unsigned)(K->cand[w][p] >> 32) : 0xffffffffu;
        }
        for (;;) {
            if (lo >= hi) { T = lo; break; }
            unsigned mid = lo + ((hi - lo) >> 1);
            unsigned c = 0;
            #pragma unroll
            for (int sl = 0; sl < 8; sl++) c += (ck[sl] <= mid) ? 1u : 0u;
            c = __reduce_add_sync(FULLMASK, c);
            if (c == KT) { T = mid; break; }
            if (c > KT) hi = mid; else lo = mid + 1;
        }
        // ---- collect <= T into buf ----
        K->buf[w][lane] = ~0ull;
        K->buf[w][lane + 32] = ~0ull;
        __syncwarp();
        int bs = 0;
        #pragma unroll
        for (int sl = 0; sl < 8; sl++) {
            int p = lane + (sl << 5);
            bool q = (ck[sl] <= T);
            unsigned mm = __ballot_sync(FULLMASK, q);
            if (q) {
                int pos = bs + __popc(mm & ((1u << lane) - 1u));
                if (pos < 64) K->buf[w][pos] = K->cand[w][p];
            }
            bs += __popc(mm);
        }
    } else {
        // ---- rare fallback: recompute keys, full 64-key search ----
        unsigned kk2[64];
        #pragma unroll
        for (int s = 0; s < 64; s++) {
            int j = lane + (s << 5);
            float4 c = K->c4[j];
            float dot = fmaf(o.x, c.x, fmaf(o.y, c.y, o.z * c.z));
            float d = fmaf(-2.0f, dot, o.w + c.w);
            unsigned u = __float_as_uint(d);
            kk2[s] = (u & 0x80000000u) ? ~u : (u | 0x80000000u);
        }
        for (;;) {
            if (lo >= hi) { T = lo; break; }
            unsigned mid = lo + ((hi - lo) >> 1);
            unsigned c = 0;
            #pragma unroll
            for (int s = 0; s < 64; s++) c += (kk2[s] <= mid) ? 1u : 0u;
            c = __reduce_add_sync(FULLMASK, c);
            if (c == KT) { T = mid; break; }
            if (c > KT) hi = mid; else lo = mid + 1;
        }
        K->buf[w][lane] = ~0ull;
        K->buf[w][lane + 32] = ~0ull;
        __syncwarp();
        int bs = 0;
        #pragma unroll
        for (int s = 0; s < 64; s++) {
            bool q = (kk2[s] <= T);
            unsigned mm = __ballot_sync(FULLMASK, q);
            if (q) {
                int pos = bs + __popc(mm & ((1u << lane) - 1u));
                if (pos < 64)
                    K->buf[w][pos] = ((ull)kk2[s] << 32) | (unsigned)(lane + (s << 5));
            }
            bs += __popc(mm);
        }
    }
    __syncwarp();

    // ---- bitonic sort of 64 u64 keys, 2 per lane -> exact (dist, idx) order
    ull v0 = K->buf[w][lane];
    ull v1 = K->buf[w][lane + 32];
    #pragma unroll
    for (int k2 = 2; k2 <= 64; k2 <<= 1) {
        #pragma unroll
        for (int j2 = k2 >> 1; j2 > 0; j2 >>= 1) {
            if (j2 == 32) {
                ull a = v0 < v1 ? v0 : v1;
                ull bm = v0 < v1 ? v1 : v0;
                v0 = a; v1 = bm;
            } else {
                bool low = ((lane & j2) == 0);
                bool up0 = ((lane & k2) == 0);
                bool up1 = (((lane + 32) & k2) == 0);
                ull o0 = __shfl_xor_sync(FULLMASK, v0, j2);
                ull o1 = __shfl_xor_sync(FULLMASK, v1, j2);
                bool t0 = (low == up0);
                bool t1 = (low == up1);
                v0 = t0 ? (v0 < o0 ? v0 : o0) : (v0 > o0 ? v0 : o0);
                v1 = t1 ? (v1 < o1 ? v1 : o1) : (v1 > o1 ? v1 : o1);
            }
        }
    }

    int* outp = g_knn + ((size_t)b * NN + n) * KT;
    outp[lane] = (int)(v0 & 0xffffffffu);
    if (lane < KT - 32) outp[32 + lane] = (int)(v1 & 0xffffffffu);
}

// ---------------------------------------------------------------------------
// Register-tiled GEMM body: O[m0..m0+64][0..128) = A @ W + bias
// ---------------------------------------------------------------------------
__device__ __forceinline__ void gemm_body(char* smraw,
                                          const float* __restrict__ A,
                                          const float* __restrict__ W,
                                          const float* __restrict__ bias,
                                          float* __restrict__ O, int m0) {
    GemmS* G = (GemmS*)smraw;
    const int t = threadIdx.x;
    const int tx = t & 31, ty = t >> 5;

    #pragma unroll
    for (int s = t; s < MT * CC / 4; s += 256) {
        int m = s >> 5, k4 = s & 31;
        float4 v = *(const float4*)&A[(size_t)(m0 + m) * CC + 4 * k4];
        G->XsT[4 * k4 + 0][m] = v.x;
        G->XsT[4 * k4 + 1][m] = v.y;
        G->XsT[4 * k4 + 2][m] = v.z;
        G->XsT[4 * k4 + 3][m] = v.w;
    }
    __syncthreads();

    ull acc[4][4];
    #pragma unroll
    for (int mp = 0; mp < 4; mp++)
        #pragma unroll
        for (int c = 0; c < 4; c++) acc[mp][c] = 0;

    #pragma unroll 8
    for (int k = 0; k < CC; k++) {
        float4 wv = __ldg(&((const float4*)W)[k * 32 + tx]);
        ull w0 = pk2(wv.x, wv.x), w1 = pk2(wv.y, wv.y);
        ull w2 = pk2(wv.z, wv.z), w3 = pk2(wv.w, wv.w);
        ulonglong2 xa = *(const ulonglong2*)&G->XsT[k][ty * 8];
        ulonglong2 xb = *(const ulonglong2*)&G->XsT[k][ty * 8 + 4];
        fma2(acc[0][0], xa.x, w0); fma2(acc[0][1], xa.x, w1);
        fma2(acc[0][2], xa.x, w2); fma2(acc[0][3], xa.x, w3);
        fma2(acc[1][0], xa.y, w0); fma2(acc[1][1], xa.y, w1);
        fma2(acc[1][2], xa.y, w2); fma2(acc[1][3], xa.y, w3);
        fma2(acc[2][0], xb.x, w0); fma2(acc[2][1], xb.x, w1);
        fma2(acc[2][2], xb.x, w2); fma2(acc[2][3], xb.x, w3);
        fma2(acc[3][0], xb.y, w0); fma2(acc[3][1], xb.y, w1);
        fma2(acc[3][2], xb.y, w2); fma2(acc[3][3], xb.y, w3);
    }

    float4 bb = *(const float4*)&bias[tx * 4];
    #pragma unroll
    for (int mp = 0; mp < 4; mp++) {
        float2 f0 = upk2(acc[mp][0]), f1 = upk2(acc[mp][1]);
        float2 f2 = upk2(acc[mp][2]), f3 = upk2(acc[mp][3]);
        int m = m0 + ty * 8 + 2 * mp;
        float4 r0 = make_float4(f0.x + bb.x, f1.x + bb.y, f2.x + bb.z, f3.x + bb.w);
        float4 r1 = make_float4(f0.y + bb.x, f1.y + bb.y, f2.y + bb.z, f3.y + bb.w);
        *(float4*)&O[(size_t)m * CC + tx * 4] = r0;
        *(float4*)&O[(size_t)(m + 1) * CC + tx * 4] = r1;
    }
}

// ---------------------------------------------------------------------------
// Fused kNN + GEMM kernel. Roles interleaved 8:5 so both kinds co-reside
// on each SM (knn = ALU/issue pipe, gemm = FMA pipe -> overlap).
// ---------------------------------------------------------------------------
__global__ __launch_bounds__(256, 3) void fused_kg_kernel(
    const float* __restrict__ coord, const float* __restrict__ pcd,
    const float* __restrict__ Wq, const float* __restrict__ bq,
    const float* __restrict__ Wk, const float* __restrict__ bk,
    const float* __restrict__ Wv, const float* __restrict__ bv) {
    extern __shared__ char smraw[];
    const int grp = blockIdx.x / 13;      // 0..255
    const int r   = blockIdx.x % 13;
    if (r < 8) {
        knn_body(smraw, coord, grp * 8 + r);           // 2048 knn blocks
    } else {
        int gid = grp * 5 + (r - 8);                   // 0..1279
        int y = gid >> 8, mblk = gid & 255;
        if (y == 0)      gemm_body(smraw, pcd, Wq, bq, g_Q, mblk * MT);
        else if (y == 1) gemm_body(smraw, pcd, Wv, bv, g_V, mblk * MT);
        else {
            int i = y - 2;
            if (mblk == 0 && threadIdx.x < CC)         // bk rows at g_KF tail
                g_KF[(size_t)(SS * BN + i) * CC + threadIdx.x] = bk[i * CC + threadIdx.x];
            gemm_body(smraw, pcd, Wk + i * CC * CC, bk + i * CC,
                      g_KF + (size_t)i * BN * CC, mblk * MT);
        }
    }
}

// ---------------------------------------------------------------------------
// Kernel 2: attention via Kf gathers. One warp per point, 8 points/block.
// ---------------------------------------------------------------------------
__global__ __launch_bounds__(256, 6) void attn_kernel(float* __restrict__ out)
{
    __shared__ int   s_kn[APP][KT];
    __shared__ float s_raw[APP][HH][56];
    __shared__ float s_attn[APP][HH];

    const int t = threadIdx.x;
    const int lane = t & 31, w = t >> 5;
    const int g = lane & 7, kq = lane >> 3;
    const int b = blockIdx.x / (NN / APP);
    const int n0 = (blockIdx.x % (NN / APP)) * APP;
    const int gbase = b * NN;

    for (int idx = t; idx < APP * KT; idx += 256) {
        int p = idx / KT, j = idx % KT;
        s_kn[p][j] = g_knn[(size_t)(gbase + n0 + p) * KT + j];
    }
    __syncthreads();

    const int n = n0 + w;

    ulonglong2 qm[4];
    {
        const float* qrow = g_Q + (size_t)(gbase + n) * CC;
        #pragma unroll
        for (int m = 0; m < 4; m++)
            qm[m] = *(const ulonglong2*)&qrow[4 * g + 32 * m];
    }

    auto job_ext = [&](int jid) -> int {
        int i = (jid >= 36) ? 2 : (jid >= 18 ? 1 : 0);
        int r = jid - 18 * i;
        if (r < 16)  return i * BN + gbase + s_kn[w][i * KNB + r];
        if (r == 16) return i * BN + gbase + n;
        return SS * BN + i;
    };
    int je0 = job_ext(lane);
    int je1 = (lane < NJOB - 32) ? job_ext(32 + lane) : je0;

    #pragma unroll
    for (int ch = 0; ch < 14; ch++) {
        int jid = (ch < 8) ? (4 * ch + kq) : (32 + 4 * (ch - 8) + kq);
        int src = (ch < 8) ? (4 * ch + kq) : (4 * (ch - 8) + kq);
        int jext = __shfl_sync(FULLMASK, (ch < 8) ? je0 : je1, src);
        const float* kf = g_KF + (size_t)jext * CC;

        ull a0 = 0, a1 = 0, a2 = 0, a3 = 0;
        {
            ulonglong2 nb0 = *(const ulonglong2*)&kf[4 * g];
            ulonglong2 nb1 = *(const ulonglong2*)&kf[4 * g + 32];
            ulonglong2 nb2 = *(const ulonglong2*)&kf[4 * g + 64];
            ulonglong2 nb3 = *(const ulonglong2*)&kf[4 * g + 96];
            fma2(a0, nb0.x, qm[0].x); fma2(a0, nb0.y, qm[0].y);
            fma2(a1, nb1.x, qm[1].x); fma2(a1, nb1.y, qm[1].y);
            fma2(a2, nb2.x, qm[2].x); fma2(a2, nb2.y, qm[2].y);
            fma2(a3, nb3.x, qm[3].x); fma2(a3, nb3.y, qm[3].y);
        }
        float2 f0 = upk2(a0), f1 = upk2(a1), f2 = upk2(a2), f3 = upk2(a3);
        float s0 = f0.x + f0.y, s1 = f1.x + f1.y;
        float s2 = f2.x + f2.y, s3 = f3.x + f3.y;
        #pragma unroll
        for (int off = 1; off <= 4; off <<= 1) {
            s0 += __shfl_xor_sync(FULLMASK, s0, off);
            s1 += __shfl_xor_sync(FULLMASK, s1, off);
            s2 += __shfl_xor_sync(FULLMASK, s2, off);
            s3 += __shfl_xor_sync(FULLMASK, s3, off);
        }
        float val = (g == 0) ? s0 : (g == 1) ? s1 : (g == 2) ? s2 : s3;
        if (g < 4 && jid < NJOB) s_raw[w][g][jid] = val;
    }
    __syncthreads();

    if (t < APP * HH) {
        const int p = t >> 2, h = t & 3;
        const float inv = 0.17677669529663687f;   // 1/sqrt(32)
        float accA = 0.0f;
        #pragma unroll
        for (int i = 0; i < SS; i++) {
            const float* raw = &s_raw[p][h][i * 18];
            float corr = raw[17] - raw[16];       // q.bk - q.Kf'[n]
            float l[KNB];
            float mx = -1e30f;
            #pragma unroll
            for (int k = 0; k < KNB; k++) {
                l[k] = inv * (raw[k] + corr);
                mx = fmaxf(mx, l[k]);
            }
            float se = 0.0f, sl = 0.0f;
            #pragma unroll
            for (int k = 0; k < KNB; k++) {
                float e = __expf(l[k] - mx);
                se += e;
                sl = fmaf(e, l[k], sl);
            }
            accA += sl / se;
        }
        s_attn[p][h] = accA;
    }
    __syncthreads();

    {
        int p = t >> 5, c4 = t & 31;
        size_t nn = (size_t)gbase + n0 + p;
        float4 vv = *(const float4*)&g_V[nn * CC + 4 * c4];
        float a = s_attn[p][c4 >> 3];
        float4 rr = make_float4(a * vv.x, a * vv.y, a * vv.z, a * vv.w);
        *(float4*)&out[nn * CC + 4 * c4] = rr;
    }
}

// ---------------------------------------------------------------------------
extern "C" void kernel_launch(void* const* d_in, const int* in_sizes, int n_in,
                              void* d_out, int out_size) {
    (void)in_sizes; (void)n_in; (void)out_size;
    const float* pcd   = (const float*)d_in[0];
    const float* coord = (const float*)d_in[1];
    const float* Wq    = (const float*)d_in[3];
    const float* bq    = (const float*)d_in[4];
    const float* Wk    = (const float*)d_in[5];
    const float* bk    = (const float*)d_in[6];
    const float* Wv    = (const float*)d_in[7];
    const float* bv    = (const float*)d_in[8];
    float* out = (float*)d_out;

    constexpr int SMEMB = (int)sizeof(KnnS) > (int)sizeof(GemmS)
                        ? (int)sizeof(KnnS) : (int)sizeof(GemmS);
    static_assert(SMEMB <= 60 * 1024, "smem");
    cudaFuncSetAttribute(fused_kg_kernel,
                         cudaFuncAttributeMaxDynamicSharedMemorySize, SMEMB);

    fused_kg_kernel<<<13 * 256, 256, SMEMB>>>(coord, pcd, Wq, bq, Wk, bk, Wv, bv);
    attn_kernel<<<BN / APP, 256>>>(out);
}